// round 8
// baseline (speedup 1.0000x reference)
#include <cuda_runtime.h>
#include <stdint.h>

#define IN_DIM 16384
#define HID    128
#define ALLN   200000
#define NODES  2000
#define SEG    100
#define NSAMP  128

// Output layout (float32):
//   [0, 256000)            positions[s][n]  (s-major)
//   [256000, 256128)       log_softmax[s]
//   [256128, 456128)       scores[0..200000)
#define OFF_LOGSM (NSAMP * NODES)
#define OFF_SCORES (NSAMP * NODES + NSAMP)

#define NPART 128

// ---------------- device scratch (no allocation allowed) ----------------
__device__ float g_hpart[NPART][HID];
__device__ float g_hs[HID];

// ---------------- XLA f32 tanh (Eigen-style rational approx) ----------------
__device__ __forceinline__ float tanh_xla(float x) {
    float ax = fabsf(x);
    if (ax < 0.0004f) return x;
    float xc = fminf(fmaxf(x, -9.0f), 9.0f);
    float x2 = xc * xc;
    float np = fmaf(x2, -2.76076847742355e-16f, 2.00018790482477e-13f);
    np = fmaf(x2, np, -8.60467152213735e-11f);
    np = fmaf(x2, np, 5.12229709037114e-08f);
    np = fmaf(x2, np, 1.48572235717979e-05f);
    np = fmaf(x2, np, 6.37261928875436e-04f);
    np = fmaf(x2, np, 4.89352455891786e-03f);
    np = np * xc;
    float dp = fmaf(x2, 1.19825839466702e-06f, 1.18534705686654e-04f);
    dp = fmaf(x2, dp, 2.26843463243900e-03f);
    dp = fmaf(x2, dp, 4.89352518554385e-03f);
    return np / dp;
}

// ---------------- threefry2x32, key=(0,42), counts=(0, i) --------------------
// Partitionable JAX scheme, 32-bit: bits[i] = out0 ^ out1.
__device__ __forceinline__ unsigned tf_xor(unsigned ctr) {
    const unsigned K0 = 0u;
    const unsigned K1 = 42u;
    const unsigned K2 = 0u ^ 42u ^ 0x1BD11BDAu;
    unsigned x0 = 0u + K0;
    unsigned x1 = ctr + K1;
#define TFR(r) { x0 += x1; x1 = __funnelshift_l(x1, x1, (r)); x1 ^= x0; }
    TFR(13) TFR(15) TFR(26) TFR(6)
    x0 += K1; x1 += K2 + 1u;
    TFR(17) TFR(29) TFR(16) TFR(24)
    x0 += K2; x1 += K0 + 2u;
    TFR(13) TFR(15) TFR(26) TFR(6)
    x0 += K0; x1 += K1 + 3u;
    TFR(17) TFR(29) TFR(16) TFR(24)
    x0 += K1; x1 += K2 + 4u;
    TFR(13) TFR(15) TFR(26) TFR(6)
    x0 += K2; x1 += K0 + 5u;
#undef TFR
    return x0 ^ x1;
}

// Exact JAX gumbel+score value (precise libdevice logf) — final arbiter only.
__device__ __forceinline__ float precise_v(unsigned ctr, float rowk) {
    unsigned b = tf_xor(ctr);
    float f = __uint_as_float((b >> 9) | 0x3f800000u) - 1.0f;
    float u = fmaxf(f, 1.17549435e-38f);
    return -logf(-logf(u)) + rowk;
}

// Fast gumbel (MUFU logs), ~2e-5 abs error; used for ranking only.
__device__ __forceinline__ float fast_g(unsigned ctr) {
    unsigned b = tf_xor(ctr);
    float f = __uint_as_float((b >> 9) | 0x3f800000u) - 1.0f;
    float u = fmaxf(f, 1.17549435e-38f);
    return -__logf(-__logf(u));
}

// ---------------- K1: float4 partials of x @ W1 ------------------------------
// 128 blocks x 256 threads; block b covers input rows [b*128, b*128+128).
// Thread: j4 = (t&31)*4 (float4 over hidden dim), grp = t>>5 handles 16 rows.
__global__ void k_h_partial(const float* __restrict__ x, const float* __restrict__ W1) {
    __shared__ float4 sm[8][32];
    int t = threadIdx.x;
    int lane = t & 31;
    int grp = t >> 5;
    int i0 = blockIdx.x * 128 + grp * 16;
    float4 acc = make_float4(0.f, 0.f, 0.f, 0.f);
#pragma unroll
    for (int ii = 0; ii < 16; ii++) {
        int i = i0 + ii;
        float xi = x[i];
        float4 w = *(const float4*)(W1 + i * HID + lane * 4);
        acc.x = fmaf(xi, w.x, acc.x);
        acc.y = fmaf(xi, w.y, acc.y);
        acc.z = fmaf(xi, w.z, acc.z);
        acc.w = fmaf(xi, w.w, acc.w);
    }
    sm[grp][lane] = acc;
    __syncthreads();
    if (t < 32) {
        float4 s = sm[0][t];
#pragma unroll
        for (int g2 = 1; g2 < 8; g2++) {
            float4 o = sm[g2][t];
            s.x += o.x; s.y += o.y; s.z += o.z; s.w += o.w;
        }
        *(float4*)(&g_hpart[blockIdx.x][t * 4]) = s;
    }
}

// ---------------- K2: reduce partials -> hs; zero log_softmax ----------------
__global__ void k_hsum(const float* __restrict__ b1, float* __restrict__ out) {
    int j = threadIdx.x;  // 128 threads
    float s = b1[j];
#pragma unroll 8
    for (int b = 0; b < NPART; b++) s += g_hpart[b][j];
    g_hs[j] = tanh_xla(s);
    out[OFF_LOGSM + j] = 0.0f;
}

// ---------------- K3 fused: prefetch W2 -> gumbel pass -> scores -> combine --
// block = node n (2000 blocks x 128 threads); thread t = sample s.
// Dynamic smem: g[SEG][128] fast-gumbel values (self-read only, no sync needed).
__global__ void __launch_bounds__(128) k_fused(const float* __restrict__ W2,
                                               const float* __restrict__ b2,
                                               float* __restrict__ out) {
    extern __shared__ float gbuf[];           // SEG*128 floats
    __shared__ float hs[HID];
    __shared__ float srow[SEG];
    __shared__ float red[8];
    __shared__ float sstat[2];
    const int n = blockIdx.x;
    const int t = threadIdx.x;
    const float NEGINF = -__int_as_float(0x7f800000);

    // --- phase 0: prefetch this block's W2 tile (128 rows x 400B) into L2 ---
    {
        const char* rowp = (const char*)(W2 + (size_t)t * ALLN + n * SEG);
        asm volatile("prefetch.global.L2 [%0];" :: "l"(rowp));
        asm volatile("prefetch.global.L2 [%0];" :: "l"(rowp + 128));
        asm volatile("prefetch.global.L2 [%0];" :: "l"(rowp + 256));
        asm volatile("prefetch.global.L2 [%0];" :: "l"(rowp + 384));
        asm volatile("prefetch.global.L2 [%0];" :: "l"(rowp + 399));
    }
    hs[t] = g_hs[t];

    // --- phase 1: gumbel pass (srow-independent); overlaps the L2 prefetch ---
    unsigned base = (unsigned)t * (unsigned)(NODES * SEG) + (unsigned)n * (unsigned)SEG;
#pragma unroll 4
    for (int k = 0; k < SEG; k++)
        gbuf[k * 128 + t] = fast_g(base + (unsigned)k);   // conflict-free STS

    __syncthreads();  // hs visible

    // --- phase 2: scores for this node's 100 columns (L2-warm loads) ---
    if (t < SEG) {
        int col = n * SEG + t;
        float acc = b2[col];
#pragma unroll 8
        for (int k = 0; k < HID; k++)
            acc = fmaf(hs[k], W2[(size_t)k * ALLN + col], acc);
        float sc = 10.0f * tanh_xla(acc);
        srow[t] = sc;
        out[OFF_SCORES + col] = sc;
    }
    __syncthreads();

    // --- phase 3: rowmax + log(sum(exp(x - max))) ---
    float v = (t < SEG) ? srow[t] : NEGINF;
#pragma unroll
    for (int off = 16; off > 0; off >>= 1)
        v = fmaxf(v, __shfl_xor_sync(0xffffffffu, v, off));
    if ((t & 31) == 0) red[t >> 5] = v;
    __syncthreads();
    if (t == 0) sstat[0] = fmaxf(fmaxf(red[0], red[1]), fmaxf(red[2], red[3]));
    __syncthreads();
    float e = (t < SEG) ? expf(srow[t] - sstat[0]) : 0.0f;
#pragma unroll
    for (int off = 16; off > 0; off >>= 1)
        e += __shfl_xor_sync(0xffffffffu, e, off);
    if ((t & 31) == 0) red[4 + (t >> 5)] = e;
    __syncthreads();
    if (t == 0) sstat[1] = logf((red[4] + red[5]) + (red[6] + red[7]));
    __syncthreads();

    // --- phase 4: combine g + srow, track top-2 ---
    float best = NEGINF, v2nd = NEGINF;
    int bk = 0, k2 = 0;
#pragma unroll 4
    for (int k = 0; k < SEG; k++) {
        float vv = gbuf[k * 128 + t] + srow[k];
        if (vv > best) { v2nd = best; k2 = bk; best = vv; bk = k; }
        else if (vv > v2nd) { v2nd = vv; k2 = k; }
    }
    // --- phase 5: precise arbitration between top-2 (tie -> smaller k) ---
    float p1 = precise_v(base + (unsigned)bk, srow[bk]);
    float p2 = precise_v(base + (unsigned)k2, srow[k2]);
    if (p2 > p1 || (p2 == p1 && k2 < bk)) bk = k2;

    out[t * NODES + n] = (float)bk;
    float lp = (srow[bk] - sstat[0]) - sstat[1];
    atomicAdd(&out[OFF_LOGSM + t], lp);
}

// ---------------- launch ----------------
extern "C" void kernel_launch(void* const* d_in, const int* in_sizes, int n_in,
                              void* d_out, int out_size) {
    const float* x  = (const float*)d_in[0];
    const float* W1 = (const float*)d_in[1];
    const float* b1 = (const float*)d_in[2];
    const float* W2 = (const float*)d_in[3];
    const float* b2 = (const float*)d_in[4];
    float* out = (float*)d_out;

    const int dynsmem = SEG * 128 * (int)sizeof(float);  // 51.2 KB
    cudaFuncSetAttribute(k_fused, cudaFuncAttributeMaxDynamicSharedMemorySize, dynsmem);

    k_h_partial<<<NPART, 256>>>(x, W1);
    k_hsum<<<1, 128>>>(b1, out);
    k_fused<<<NODES, 128, dynsmem>>>(W2, b2, out);
}

// round 9
// speedup vs baseline: 1.1091x; 1.1091x over previous
#include <cuda_runtime.h>
#include <stdint.h>

#define IN_DIM 16384
#define HID    128
#define ALLN   200000
#define NODES  2000
#define SEG    100
#define NSAMP  128

// Output layout (float32):
//   [0, 256000)            positions[s][n]  (s-major)
//   [256000, 256128)       log_softmax[s]
//   [256128, 456128)       scores[0..200000)
#define OFF_LOGSM (NSAMP * NODES)
#define OFF_SCORES (NSAMP * NODES + NSAMP)

#define NPART 512

// ---------------- device scratch (no allocation allowed) ----------------
__device__ float g_hpart[NPART][HID];
__device__ float g_hs[HID];

// ---------------- XLA f32 tanh (Eigen-style rational approx) ----------------
__device__ __forceinline__ float tanh_xla(float x) {
    float ax = fabsf(x);
    if (ax < 0.0004f) return x;
    float xc = fminf(fmaxf(x, -9.0f), 9.0f);
    float x2 = xc * xc;
    float np = fmaf(x2, -2.76076847742355e-16f, 2.00018790482477e-13f);
    np = fmaf(x2, np, -8.60467152213735e-11f);
    np = fmaf(x2, np, 5.12229709037114e-08f);
    np = fmaf(x2, np, 1.48572235717979e-05f);
    np = fmaf(x2, np, 6.37261928875436e-04f);
    np = fmaf(x2, np, 4.89352455891786e-03f);
    np = np * xc;
    float dp = fmaf(x2, 1.19825839466702e-06f, 1.18534705686654e-04f);
    dp = fmaf(x2, dp, 2.26843463243900e-03f);
    dp = fmaf(x2, dp, 4.89352518554385e-03f);
    return np / dp;
}

// ---------------- threefry2x32, key=(0,42), counts=(0, i) --------------------
// Partitionable JAX scheme, 32-bit: bits[i] = out0 ^ out1.
__device__ __forceinline__ unsigned tf_xor(unsigned ctr) {
    const unsigned K0 = 0u;
    const unsigned K1 = 42u;
    const unsigned K2 = 0u ^ 42u ^ 0x1BD11BDAu;
    unsigned x0 = 0u + K0;
    unsigned x1 = ctr + K1;
#define TFR(r) { x0 += x1; x1 = __funnelshift_l(x1, x1, (r)); x1 ^= x0; }
    TFR(13) TFR(15) TFR(26) TFR(6)
    x0 += K1; x1 += K2 + 1u;
    TFR(17) TFR(29) TFR(16) TFR(24)
    x0 += K2; x1 += K0 + 2u;
    TFR(13) TFR(15) TFR(26) TFR(6)
    x0 += K0; x1 += K1 + 3u;
    TFR(17) TFR(29) TFR(16) TFR(24)
    x0 += K1; x1 += K2 + 4u;
    TFR(13) TFR(15) TFR(26) TFR(6)
    x0 += K2; x1 += K0 + 5u;
#undef TFR
    return x0 ^ x1;
}

// Exact JAX gumbel+score value (precise libdevice logf) — final arbiter only.
__device__ __forceinline__ float precise_v(unsigned ctr, float rowk) {
    unsigned b = tf_xor(ctr);
    float f = __uint_as_float((b >> 9) | 0x3f800000u) - 1.0f;
    float u = fmaxf(f, 1.17549435e-38f);
    return -logf(-logf(u)) + rowk;
}

// ---------------- K1: float4 partials of x @ W1 ------------------------------
// 512 blocks x 128 threads; block b covers input rows [b*32, b*32+32).
// lane = j4 index (32 lanes x float4 = 128 hidden), grp = t>>5 handles 8 rows.
__global__ void k_h_partial(const float* __restrict__ x, const float* __restrict__ W1) {
    __shared__ float4 sm[4][32];
    int t = threadIdx.x;
    int lane = t & 31;
    int grp = t >> 5;
    int i0 = blockIdx.x * 32 + grp * 8;
    float4 acc = make_float4(0.f, 0.f, 0.f, 0.f);
#pragma unroll
    for (int ii = 0; ii < 8; ii++) {
        int i = i0 + ii;
        float xi = x[i];
        float4 w = *(const float4*)(W1 + i * HID + lane * 4);
        acc.x = fmaf(xi, w.x, acc.x);
        acc.y = fmaf(xi, w.y, acc.y);
        acc.z = fmaf(xi, w.z, acc.z);
        acc.w = fmaf(xi, w.w, acc.w);
    }
    sm[grp][lane] = acc;
    __syncthreads();
    if (t < 32) {
        float4 a = sm[0][t], b = sm[1][t], c = sm[2][t], d = sm[3][t];
        float4 s;
        s.x = (a.x + b.x) + (c.x + d.x);
        s.y = (a.y + b.y) + (c.y + d.y);
        s.z = (a.z + b.z) + (c.z + d.z);
        s.w = (a.w + b.w) + (c.w + d.w);
        *(float4*)(&g_hpart[blockIdx.x][t * 4]) = s;
    }
}

// ---------------- K2: reduce partials -> hs; zero log_softmax ----------------
// 512 threads: 4 summers per column, smem combine.
__global__ void k_hsum(const float* __restrict__ b1, float* __restrict__ out) {
    __shared__ float sm[512];
    int t = threadIdx.x;
    int j = t & 127;
    int q = t >> 7;          // 0..3, sums blocks [q*128, q*128+128)
    float s = 0.0f;
#pragma unroll 8
    for (int b = 0; b < NPART / 4; b++) s += g_hpart[q * (NPART / 4) + b][j];
    sm[t] = s;
    __syncthreads();
    if (t < 128) {
        float tot = b1[j] + ((sm[j] + sm[j + 128]) + (sm[j + 256] + sm[j + 384]));
        g_hs[j] = tanh_xla(tot);
        out[OFF_LOGSM + j] = 0.0f;
    }
}

// ---------------- K3 fused: scores + rowstats + gumbel sampling --------------
// block = node n (2000 blocks x 128 threads); thread t = sample s.
__global__ void __launch_bounds__(128) k_fused(const float* __restrict__ W2,
                                               const float* __restrict__ b2,
                                               float* __restrict__ out) {
    __shared__ float hs[HID];
    __shared__ float srow[SEG];
    __shared__ float negsexp[SEG];   // -exp(-srow[k]) for one-MUFU ranking
    __shared__ float red[8];
    __shared__ float sstat[2];       // rowmax, log(sumexp)
    const int n = blockIdx.x;
    const int t = threadIdx.x;
    const float NEGINF = -__int_as_float(0x7f800000);
    const float POSINF =  __int_as_float(0x7f800000);

    hs[t] = g_hs[t];
    __syncthreads();

    // --- scores for this node's 100 columns (coalesced over t) ---
    if (t < SEG) {
        int col = n * SEG + t;
        float acc = b2[col];
#pragma unroll 8
        for (int k = 0; k < HID; k++)
            acc = fmaf(hs[k], W2[(size_t)k * ALLN + col], acc);
        float sc = 10.0f * tanh_xla(acc);
        srow[t] = sc;
        negsexp[t] = -expf(-sc);
        out[OFF_SCORES + col] = sc;
    }
    __syncthreads();

    // --- rowmax ---
    float v = (t < SEG) ? srow[t] : NEGINF;
#pragma unroll
    for (int off = 16; off > 0; off >>= 1)
        v = fmaxf(v, __shfl_xor_sync(0xffffffffu, v, off));
    if ((t & 31) == 0) red[t >> 5] = v;
    __syncthreads();
    if (t == 0) sstat[0] = fmaxf(fmaxf(red[0], red[1]), fmaxf(red[2], red[3]));
    __syncthreads();

    // --- log(sum(exp(x - max))) ---
    float e = (t < SEG) ? expf(srow[t] - sstat[0]) : 0.0f;
#pragma unroll
    for (int off = 16; off > 0; off >>= 1)
        e += __shfl_xor_sync(0xffffffffu, e, off);
    if ((t & 31) == 0) red[4 + (t >> 5)] = e;
    __syncthreads();
    if (t == 0) sstat[1] = logf((red[4] + red[5]) + (red[6] + red[7]));
    __syncthreads();

    // --- sampling: thread t = sample s ---
    // argmax_k (g_k + srow_k) == argmin_k m'_k with
    //   m'_k = lg2(u_k) * (-exp(-srow_k))   (> 0; one MUFU per gumbel)
    // track top-2, then arbitrate with the exact JAX expression.
    unsigned base = (unsigned)t * (unsigned)(NODES * SEG) + (unsigned)n * (unsigned)SEG;
    float m1 = POSINF, m2 = POSINF;
    int bk = 0, k2 = 0;
#pragma unroll 10
    for (int k = 0; k < SEG; k++) {
        unsigned b = tf_xor(base + (unsigned)k);
        float f = __uint_as_float((b >> 9) | 0x3f800000u) - 1.0f;
        float u = fmaxf(f, 1.17549435e-38f);
        float m = __log2f(u) * negsexp[k];     // lg2(u) < 0, negsexp < 0 -> m > 0
        if (m < m1) { m2 = m1; k2 = bk; m1 = m; bk = k; }
        else if (m < m2) { m2 = m; k2 = k; }
    }
    // precise arbitration between the two fast candidates (tie -> smaller k)
    float p1 = precise_v(base + (unsigned)bk, srow[bk]);
    float p2 = precise_v(base + (unsigned)k2, srow[k2]);
    if (p2 > p1 || (p2 == p1 && k2 < bk)) bk = k2;

    out[t * NODES + n] = (float)bk;
    float lp = (srow[bk] - sstat[0]) - sstat[1];
    atomicAdd(&out[OFF_LOGSM + t], lp);
}

// ---------------- launch ----------------
extern "C" void kernel_launch(void* const* d_in, const int* in_sizes, int n_in,
                              void* d_out, int out_size) {
    const float* x  = (const float*)d_in[0];
    const float* W1 = (const float*)d_in[1];
    const float* b1 = (const float*)d_in[2];
    const float* W2 = (const float*)d_in[3];
    const float* b2 = (const float*)d_in[4];
    float* out = (float*)d_out;

    k_h_partial<<<NPART, 128>>>(x, W1);
    k_hsum<<<1, 512>>>(b1, out);
    k_fused<<<NODES, 128>>>(W2, b2, out);
}